// round 17
// baseline (speedup 1.0000x reference)
#include <cuda_runtime.h>
#include <math.h>

#define B 8
#define T 512
#define C 512
#define DFF 2048
#define H 8
#define LYR 6
#define W 4
#define DK 64
#define NREL 9

typedef unsigned long long u64;
typedef unsigned int u32;

#define QS2  (32*12*1024)
#define OS2  (32*4*1024)
#define W1S2 (3*32*16*1024)
#define W2S2 (3*128*4*1024)

// ---------------- scratch ----------------------------------------------------
__device__ float g_h[B*C*T];
__device__ float g_qkv[B*3*C*T];
__device__ float g_y[B*C*T];
__device__ float g_mask[B*T];
__device__ float g_b3[LYR*3*C];
__device__ u32 g_px512_hi[B*8*32*516],   g_px512_lo[B*8*32*516];
__device__ u32 g_px2048_hi[B*32*32*516], g_px2048_lo[B*32*32*516];
// double-buffered per-layer weight fragments (parity = layer & 1)
__device__ u32 g_wqkv_hi[2*QS2],  g_wqkv_lo[2*QS2];
__device__ u32 g_wo_hi[2*OS2],    g_wo_lo[2*OS2];
__device__ u32 g_w1_hi[2*W1S2],   g_w1_lo[2*W1S2];
__device__ u32 g_w2_hi[2*W2S2],   g_w2_lo[2*W2S2];
__device__ u32 g_pj_hi[32*8*1024], g_pj_lo[32*8*1024];

// ---------------- helpers ------------------------------------------------------
__device__ __forceinline__ u64 ffma2(u64 a, u64 b, u64 c) {
    u64 d; asm("fma.rn.f32x2 %0, %1, %2, %3;" : "=l"(d) : "l"(a), "l"(b), "l"(c));
    return d;
}
__device__ __forceinline__ u64 fpack2(float lo, float hi) {
    u64 d; asm("mov.b64 %0, {%1, %2};" : "=l"(d) : "f"(lo), "f"(hi));
    return d;
}
__device__ __forceinline__ float2 funpack2(u64 v) {
    float2 r; asm("mov.b64 {%0, %1}, %2;" : "=f"(r.x), "=f"(r.y) : "l"(v));
    return r;
}
__device__ __forceinline__ u32 bf2(float h, float l) {
    u32 r; asm("cvt.rn.bf16x2.f32 %0, %1, %2;" : "=r"(r) : "f"(h), "f"(l));
    return r;
}
__device__ __forceinline__ void split2(float f0, float f1, u32& hv, u32& lv) {
    hv = bf2(f1, f0);
    float r0 = f0 - __uint_as_float(hv << 16);
    float r1 = f1 - __uint_as_float(hv & 0xffff0000u);
    lv = bf2(r1, r0);
}
__device__ __forceinline__ void mma16(float* d, const u32* a, u32 b0, u32 b1) {
    asm("mma.sync.aligned.m16n8k16.row.col.f32.bf16.bf16.f32 "
        "{%0,%1,%2,%3}, {%4,%5,%6,%7}, {%8,%9}, {%0,%1,%2,%3};"
        : "+f"(d[0]), "+f"(d[1]), "+f"(d[2]), "+f"(d[3])
        : "r"(a[0]), "r"(a[1]), "r"(a[2]), "r"(a[3]), "r"(b0), "r"(b1));
}
__device__ __forceinline__ u32 smem_u32(const void* p) {
    u32 a; asm("{ .reg .u64 t; cvta.to.shared.u64 t, %1; cvt.u32.u64 %0, t; }"
               : "=r"(a) : "l"(p));
    return a;
}
__device__ __forceinline__ void cp16(u32 dst, const void* src) {
    asm volatile("{ .reg .u64 g; cvta.to.global.u64 g, %1; "
                 "cp.async.cg.shared.global [%0], [g], 16; }"
                 :: "r"(dst), "l"(src) : "memory");
}

// ---------------- pad zeroing ----------------------------------------------------
__global__ void k_zpad() {
    int r = blockIdx.x*256 + threadIdx.x;
    u32 *hi, *lo; int row;
    if (r < 2048)       { hi = g_px512_hi;  lo = g_px512_lo;  row = r; }
    else if (r < 10240) { hi = g_px2048_hi; lo = g_px2048_lo; row = r - 2048; }
    else return;
    size_t base = (size_t)row * 516;
    hi[base] = 0u;     lo[base] = 0u;
    hi[base+513] = 0u; lo[base+513] = 0u;
    hi[base+514] = 0u; lo[base+514] = 0u;
    hi[base+515] = 0u; lo[base+515] = 0u;
}

// ---------------- embedding + mask + qkv-input panel ----------------------------
__global__ void k_embed(const int* __restrict__ x, const int* __restrict__ xlen,
                        const float* __restrict__ emb,
                        float* __restrict__ out_xemb, float* __restrict__ out_mask) {
    int b = blockIdx.y;
    int t = blockIdx.x * 32 + threadIdx.x;
    int xi = x[b*T + t];
    float mk = (t < xlen[b]) ? 1.f : 0.f;
    const float SQ = 22.627416997969522f;
    for (int p = threadIdx.y; p < 256; p += 8) {
        int c0 = 2*p;
        float v0 = emb[xi*C + c0] * SQ;
        float v1 = emb[xi*C + c0 + 1] * SQ;
        out_xemb[((size_t)b*C + c0)*T + t] = v0;
        out_xemb[((size_t)b*C + c0 + 1)*T + t] = v1;
        float h0 = v0*mk, h1 = v1*mk;
        g_h[((size_t)b*C + c0)*T + t] = h0;
        g_h[((size_t)b*C + c0 + 1)*T + t] = h1;
        u32 hv, lv; split2(h0, h1, hv, lv);
        size_t pb = ((size_t)(b*8 + (p >> 5))*32 + (p & 31))*516 + t + 1;
        g_px512_hi[pb] = hv; g_px512_lo[pb] = lv;
    }
    if (threadIdx.y == 0) {
        g_mask[b*T + t] = mk;
        out_mask[b*T + t] = mk;
    }
}

__global__ void k_copy4(const float4* __restrict__ src, float4* __restrict__ dst) {
    int i = blockIdx.x * 256 + threadIdx.x;
    dst[i] = src[i];
}

__global__ void k_bias3(const float* __restrict__ bq, const float* __restrict__ bk,
                        const float* __restrict__ bv, float* __restrict__ b3) {
    int l = blockIdx.y;
    int i = blockIdx.x*256 + threadIdx.x;
    float v;
    if (i < 512)       v = bq[l*C + i] * 0.125f;
    else if (i < 1024) v = bk[l*C + i - 512];
    else               v = bv[l*C + i - 1024];
    b3[l*1536 + i] = v;
}

// ---------------- generic weight pack (proj only) -------------------------------
__global__ void k_packwf(const float* __restrict__ Wm, float scale,
                         u32* __restrict__ hi, u32* __restrict__ lo,
                         int ostride, int KKf, int CT16, int OT, int otOff) {
    int ot = blockIdx.x, c16 = blockIdx.y, kp = blockIdx.z;
    int tid = threadIdx.x, s = tid >> 5, l = tid & 31;
    int g = l >> 2, tq = l & 3;
    int wm = s >> 2, mi = s & 3;
    int obase = ot*128 + wm*64 + mi*16 + g;
    u32 rh[4], rl[4];
#pragma unroll
    for (int r = 0; r < 4; r++) {
        int o = obase + (r & 1)*8;
        int pair = (r < 2) ? tq : tq + 4;
        int ce = c16*16 + 2*pair;
        float f0 = Wm[(size_t)o*ostride + (size_t)ce*KKf + kp] * scale;
        float f1 = Wm[(size_t)o*ostride + (size_t)(ce+1)*KKf + kp] * scale;
        split2(f0, f1, rh[r], rl[r]);
    }
    size_t base = ((size_t)((kp*CT16 + c16)*OT + otOff + ot))*1024 + (s*32 + l)*4;
    *(uint4*)&hi[base] = make_uint4(rh[0], rh[1], rh[2], rh[3]);
    *(uint4*)&lo[base] = make_uint4(rl[0], rl[1], rl[2], rl[3]);
}

// ---------------- merged per-layer weight pack ----------------------------------
__global__ void k_packall(const float* __restrict__ Wq, const float* __restrict__ Wk,
                          const float* __restrict__ Wv, const float* __restrict__ Wo,
                          const float* __restrict__ w1, const float* __restrict__ w2,
                          u32* __restrict__ qh, u32* __restrict__ ql,
                          u32* __restrict__ oh, u32* __restrict__ ol,
                          u32* __restrict__ w1h, u32* __restrict__ w1l,
                          u32* __restrict__ w2h, u32* __restrict__ w2l) {
    int bx = blockIdx.x;
    const float* Wm; float scale = 1.f;
    u32 *hi, *lo;
    int ostride, KKf, CT16, OT, otOff, ot, c16, kp;
    if (bx < 512) {
        int m = bx >> 7, r = bx & 127;
        ot = r & 3; c16 = r >> 2; kp = 0;
        ostride = C; KKf = 1; CT16 = 32;
        if (m == 0)      { Wm = Wq; scale = 0.125f; hi = qh; lo = ql; OT = 12; otOff = 0; }
        else if (m == 1) { Wm = Wk; hi = qh; lo = ql; OT = 12; otOff = 4; }
        else if (m == 2) { Wm = Wv; hi = qh; lo = ql; OT = 12; otOff = 8; }
        else             { Wm = Wo; hi = oh; lo = ol; OT = 4;  otOff = 0; }
    } else if (bx < 2048) {
        int r = bx - 512;
        ot = r & 15; c16 = (r >> 4) & 31; kp = r >> 9;
        Wm = w1; hi = w1h; lo = w1l; ostride = C*3; KKf = 3; CT16 = 32; OT = 16; otOff = 0;
    } else {
        int r = bx - 2048;
        ot = r & 3; c16 = (r >> 2) & 127; kp = r >> 9;
        Wm = w2; hi = w2h; lo = w2l; ostride = DFF*3; KKf = 3; CT16 = 128; OT = 4; otOff = 0;
    }
    int tid = threadIdx.x, s = tid >> 5, l = tid & 31;
    int g = l >> 2, tq = l & 3;
    int wm = s >> 2, mi = s & 3;
    int obase = ot*128 + wm*64 + mi*16 + g;
    u32 rh[4], rl[4];
#pragma unroll
    for (int r = 0; r < 4; r++) {
        int o = obase + (r & 1)*8;
        int pair = (r < 2) ? tq : tq + 4;
        int ce = c16*16 + 2*pair;
        float f0 = Wm[(size_t)o*ostride + (size_t)ce*KKf + kp] * scale;
        float f1 = Wm[(size_t)o*ostride + (size_t)(ce+1)*KKf + kp] * scale;
        split2(f0, f1, rh[r], rl[r]);
    }
    size_t base = ((size_t)((kp*CT16 + c16)*OT + otOff + ot))*1024 + (s*32 + l)*4;
    *(uint4*)&hi[base] = make_uint4(rh[0], rh[1], rh[2], rh[3]);
    *(uint4*)&lo[base] = make_uint4(rl[0], rl[1], rl[2], rl[3]);
}

// ---------------- fragment-direct bf16 mma GEMM/conv ---------------------------
#define LOADA4(BI, ct_, kp_, k16_) do { \
    size_t ab_ = ((size_t)(((kp_)*CT16 + (ct_)*4 + (k16_))*OT + oy)) << 8; \
    const uint4* Abh_ = (const uint4*)Whi + ab_; \
    const uint4* Abl_ = (const uint4*)Wlo + ab_; \
    _Pragma("unroll") \
    for (int mi_ = 0; mi_ < 4; mi_++) { \
        int s_ = (wm*4 + mi_)*32 + lane; \
        ah[BI][mi_] = Abh_[s_]; al[BI][mi_] = Abl_[s_]; \
    } \
} while (0)

template<int KK, int NT, int PACK>
__global__ __launch_bounds__(256, 1) void k_mma_f(
        const u32* __restrict__ Whi, const u32* __restrict__ Wlo,
        const u32* __restrict__ Xhi, const u32* __restrict__ Xlo,
        const float* __restrict__ bias,
        float* __restrict__ Y0, float* __restrict__ Y1, int Osplit,
        u32* __restrict__ PanHi, u32* __restrict__ PanLo, int CTpan,
        int Cin, int relu, int maskOut) {
    extern __shared__ char smc[];
    const int STG = 64*136;
    const int CHUNKS = 33;
    const int PAD = (KK - 1) / 2;
    const int U = KK*4;
    u32 sb = smem_u32(smc);
    int tid = threadIdx.x, warp = tid >> 5, lane = tid & 31;
    int g = lane >> 2, tq = lane & 3;
    int wm = warp >> 2, wn = warp & 3;
    int t0 = blockIdx.x*NT, oy = blockIdx.y, b = blockIdx.z;
    int OT = gridDim.y;
    int CT = Cin >> 6, CT16 = Cin >> 4;
    const float* mrow = g_mask + b*T;

    float acc[4][4][4];
#pragma unroll
    for (int mi = 0; mi < 4; mi++)
#pragma unroll
        for (int ni = 0; ni < 4; ni++)
#pragma unroll
            for (int q = 0; q < 4; q++) acc[mi][ni][q] = 0.f;

#pragma unroll
    for (int st = 0; st < 3; st++) {
        size_t prow = (size_t)(b*CT + st)*32;
        for (int e = tid; e < 64*CHUNKS; e += 256) {
            int r = e / CHUNKS, cch = e - r*CHUNKS;
            const u32* src = ((r < 32) ? Xhi : Xlo) + (prow + (r & 31))*516 + t0 + cch*4;
            cp16(sb + (u32)(st*STG + r*136 + cch*4)*4, src);
        }
        asm volatile("cp.async.commit_group;" ::: "memory");
    }

    uint4 ah[4][4], al[4][4];
    LOADA4(0, 0, 0, 0);
    LOADA4(1, 0, 0, 1);
    LOADA4(2, 0, 0, 2);

    for (int ct = 0; ct < CT; ct++) {
        asm volatile("cp.async.wait_group 2;" ::: "memory");
        __syncthreads();
        if (ct + 3 < CT) {
            int stg = (ct + 3) & 3;
            size_t prow = (size_t)(b*CT + ct + 3)*32;
            for (int e = tid; e < 64*CHUNKS; e += 256) {
                int r = e / CHUNKS, cch = e - r*CHUNKS;
                const u32* src = ((r < 32) ? Xhi : Xlo) + (prow + (r & 31))*516 + t0 + cch*4;
                cp16(sb + (u32)(stg*STG + r*136 + cch*4)*4, src);
            }
        }
        asm volatile("cp.async.commit_group;" ::: "memory");

        const u32* Bst = (const u32*)smc + (ct & 3)*STG;
#pragma unroll
        for (int ui = 0; ui < U; ui++) {
            const int kp = ui >> 2, k16 = ui & 3;
            const int ccoff = kp + 1 - PAD;
            const int pf = ui + 3;
            const int pb = pf & 3;
            if (pf < U) {
                LOADA4(pb, ct, (pf >> 2), (pf & 3));
            } else if (ct + 1 < CT) {
                const int p2 = pf - U;
                LOADA4(pb, ct + 1, (p2 >> 2), (p2 & 3));
            }
            const int cb = ui & 3;
            int rb = k16*8;
#pragma unroll
            for (int ni = 0; ni < 4; ni++) {
                int cc = wn*32 + ni*8 + g + ccoff;
                u32 bh0 = Bst[(rb+tq)*136 + cc];
                u32 bh1 = Bst[(rb+tq+4)*136 + cc];
                u32 bl0 = Bst[(32+rb+tq)*136 + cc];
                u32 bl1 = Bst[(32+rb+tq+4)*136 + cc];
#pragma unroll
                for (int mi = 0; mi < 4; mi++) {
                    mma16(acc[mi][ni], (const u32*)&al[cb][mi], bh0, bh1);
                    mma16(acc[mi][ni], (const u32*)&ah[cb][mi], bl0, bl1);
                    mma16(acc[mi][ni], (const u32*)&ah[cb][mi], bh0, bh1);
                }
            }
        }
    }
    __syncthreads();
    if (PACK == 0) {
#pragma unroll
        for (int mi = 0; mi < 4; mi++) {
#pragma unroll
            for (int half = 0; half < 2; half++) {
                int o = oy*128 + wm*64 + mi*16 + g + half*8;
                float bi = bias[o];
                float* Yp; size_t rowb;
                if (o < Osplit) { Yp = Y0; rowb = ((size_t)b*Osplit + o)*T; }
                else            { Yp = Y1; rowb = ((size_t)b*Osplit + (o - Osplit))*T; }
#pragma unroll
                for (int ni = 0; ni < 4; ni++) {
                    int t = t0 + wn*32 + ni*8 + 2*tq;
                    float v0 = acc[mi][ni][half*2 + 0] + bi;
                    float v1 = acc[mi][ni][half*2 + 1] + bi;
                    if (relu) { v0 = fmaxf(v0, 0.f); v1 = fmaxf(v1, 0.f); }
                    if (maskOut) { v0 *= mrow[t]; v1 *= mrow[t+1]; }
                    *(float2*)&Yp[rowb + t] = make_float2(v0, v1);
                }
            }
        }
    } else {
#pragma unroll
        for (int mi = 0; mi < 4; mi++) {
#pragma unroll
            for (int half = 0; half < 2; half++) {
                int o = oy*128 + wm*64 + mi*16 + g + half*8;
                float bi = bias[o];
                size_t pbase = ((size_t)(b*CTpan + (o >> 6))*32 + ((o & 63) >> 1))*516;
#pragma unroll
                for (int ni = 0; ni < 4; ni++) {
                    int t = t0 + wn*32 + ni*8 + 2*tq;
                    float v0 = acc[mi][ni][half*2 + 0] + bi;
                    float v1 = acc[mi][ni][half*2 + 1] + bi;
                    if (relu) { v0 = fmaxf(v0, 0.f); v1 = fmaxf(v1, 0.f); }
                    v0 *= mrow[t]; v1 *= mrow[t+1];
                    float p0 = __shfl_xor_sync(0xffffffffu, v0, 4);
                    float p1 = __shfl_xor_sync(0xffffffffu, v1, 4);
                    if (!(g & 1)) {
                        u32 h0, l0, h1, l1;
                        split2(v0, p0, h0, l0);
                        split2(v1, p1, h1, l1);
                        PanHi[pbase + t + 1] = h0; PanHi[pbase + t + 2] = h1;
                        PanLo[pbase + t + 1] = l0; PanLo[pbase + t + 2] = l1;
                    }
                }
            }
        }
    }
}

// ---------------- fused flash attention -> packed ctx panels -------------------
#define OFF_Q   0
#define OFF_KV  34816
#define OFF_PS  52224
#define OFF_BND 86016
#define OFF_BAC 91136
#define OFF_RKS 96256
#define OFF_RVS 98704
#define OFF_MS  101152
#define OFF_MTV 103200
#define OFF_MRO 103712
#define OFF_SSM 104224
#define OFF_SCL 104736
#define FSM_TOTAL 105248
__global__ __launch_bounds__(256, 2) void k_flash(
        const float* __restrict__ qkv,
        u32* __restrict__ PanHi, u32* __restrict__ PanLo,
        const float* __restrict__ rk_g, const float* __restrict__ rv_g) {
    extern __shared__ char fsm[];
    float* Qs   = (float*)(fsm + OFF_Q);
    float* Ks   = (float*)(fsm + OFF_KV);
    u64*   Vd   = (u64*)(fsm + OFF_KV);
    float* Ps   = (float*)(fsm + OFF_PS);
    float* bnd  = (float*)(fsm + OFF_BND);
    float* bacc = (float*)(fsm + OFF_BAC);
    float* rks  = (float*)(fsm + OFF_RKS);
    float* rvs  = (float*)(fsm + OFF_RVS);
    float* ms   = (float*)(fsm + OFF_MS);
    float* mtv  = (float*)(fsm + OFF_MTV);
    float* mro  = (float*)(fsm + OFF_MRO);
    float* ssum = (float*)(fsm + OFF_SSM);
    float* scal = (float*)(fsm + OFF_SCL);

    int lid = threadIdx.x;
    int t0 = blockIdx.x * 128;
    int bh = blockIdx.y, b = bh >> 3, h = bh & 7;
    const float* qb = qkv + ((size_t)b*1536 + h*DK)*T;
    const float* kb = qkv + ((size_t)b*1536 + 512 + h*DK)*T;
    const float* vb = qkv + ((size_t)b*1536 + 1024 + h*DK)*T;
    int txq = lid & 7,  tyq = lid >> 3;
    int txc = lid & 15, tyc = lid >> 4;

#pragma unroll
    for (int it = 0; it < 32; it++) {
        int e = lid + it*256;
        int tloc = e & 127, dd = e >> 7;
        Qs[tloc*68 + dd] = qb[(size_t)dd*T + t0 + tloc];
    }
    for (int e = lid; e < 9*64; e += 256) {
        rks[(e >> 6)*68 + (e & 63)] = rk_g[e];
        rvs[(e >> 6)*68 + (e & 63)] = rv_g[e];
    }
    for (int e = lid; e < T; e += 256) ms[e] = g_mask[b*T + e];
    if (lid < 128) {
        mtv[lid] = g_mask[b*T + t0 + lid];
        mro[lid] = -3.4e38f;
        ssum[lid] = 0.f;
    }
    for (int e = lid; e < 128*10; e += 256) bacc[e] = 0.f;
    __syncthreads();
    for (int e = lid; e < 128*9; e += 256) {
        int t = e / 9, dt = e - t*9;
        float dot = 0.f;
#pragma unroll
        for (int d = 0; d < 64; d++)
            dot += Qs[t*68 + d] * rks[dt*68 + d];
        bnd[t*10 + dt] = dot;
    }

    u64 oacc[4][4];
#pragma unroll
    for (int i = 0; i < 4; i++)
#pragma unroll
        for (int j = 0; j < 4; j++) oacc[i][j] = 0ull;

    for (int s0 = 0; s0 < T; s0 += 64) {
        __syncthreads();
#pragma unroll
        for (int it = 0; it < 16; it++) {
            int e = lid + it*256;
            int dd = e >> 6, ss = e & 63;
            Ks[dd*68 + ss] = kb[(size_t)dd*T + s0 + ss];
        }
        __syncthreads();
        u64 sacc[4][4];
#pragma unroll
        for (int i = 0; i < 4; i++)
#pragma unroll
            for (int j = 0; j < 4; j++) sacc[i][j] = 0ull;
#pragma unroll 16
        for (int kk = 0; kk < 64; kk++) {
            ulonglong2 xa = *(const ulonglong2*)&Ks[kk*68 + txq*8];
            ulonglong2 xb = *(const ulonglong2*)&Ks[kk*68 + txq*8 + 4];
#pragma unroll
            for (int i = 0; i < 4; i++) {
                float qv = Qs[(tyq*4+i)*68 + kk];
                u64 w = fpack2(qv, qv);
                sacc[i][0] = ffma2(w, xa.x, sacc[i][0]);
                sacc[i][1] = ffma2(w, xa.y, sacc[i][1]);
                sacc[i][2] = ffma2(w, xb.x, sacc[i][2]);
                sacc[i][3] = ffma2(w, xb.y, sacc[i][3]);
            }
        }
        float sv[4][8];
#pragma unroll
        for (int i = 0; i < 4; i++) {
            int tl = tyq*4 + i;
            float mt = mtv[tl];
            float rmax = -3.4e38f;
#pragma unroll
            for (int jp = 0; jp < 4; jp++) {
                float2 f = funpack2(sacc[i][jp]);
                sv[i][2*jp] = f.x; sv[i][2*jp+1] = f.y;
            }
#pragma unroll
            for (int j = 0; j < 8; j++) {
                int sg = s0 + txq*8 + j;
                float v = sv[i][j];
                int dtix = sg - (t0 + tl) + W;
                if ((unsigned)dtix < 9u) v += bnd[tl*10 + dtix];
                if (mt * ms[sg] == 0.f) v = -1e4f;
                sv[i][j] = v;
                rmax = fmaxf(rmax, v);
            }
#pragma unroll
            for (int o = 1; o <= 4; o <<= 1)
                rmax = fmaxf(rmax, __shfl_xor_sync(0xffffffffu, rmax, o));
            if (txq == 0) {
                float old = mro[tl];
                float nm = fmaxf(old, rmax);
                scal[tl] = expf(old - nm);
                mro[tl] = nm;
            }
        }
        __syncthreads();
#pragma unroll
        for (int i = 0; i < 4; i++) {
            int tl = tyq*4 + i;
            float nm = mro[tl];
            float cs = 0.f;
#pragma unroll
            for (int j = 0; j < 8; j++) {
                float e = expf(sv[i][j] - nm);
                cs += e;
                Ps[(txq*8 + j)*132 + tl] = e;
            }
#pragma unroll
            for (int o = 1; o <= 4; o <<= 1)
                cs += __shfl_xor_sync(0xffffffffu, cs, o);
            if (txq == 0) ssum[tl] = ssum[tl]*scal[tl] + cs;
        }
        __syncthreads();
        for (int e = lid; e < 128*9; e += 256) {
            int t = e / 9, dt = e - t*9;
            float v = bacc[t*10 + dt] * scal[t];
            int sg = t0 + t + dt - W;
            if (sg >= s0 && sg < s0 + 64) v += Ps[(sg - s0)*132 + t];
            bacc[t*10 + dt] = v;
        }
#pragma unroll
        for (int jp = 0; jp < 4; jp++) {
            int tp = txc*4 + jp;
            float se = scal[2*tp], so = scal[2*tp + 1];
#pragma unroll
            for (int i = 0; i < 4; i++) {
                float2 f = funpack2(oacc[i][jp]);
                oacc[i][jp] = fpack2(f.x*se, f.y*so);
            }
        }
#pragma unroll
        for (int sub = 0; sub < 2; sub++) {
            __syncthreads();
#pragma unroll
            for (int it = 0; it < 8; it++) {
                int e = lid + it*256;
                int dd = e >> 5, ss = e & 31;
                float v = vb[(size_t)dd*T + s0 + sub*32 + ss];
                Vd[dd*33 + ss] = fpack2(v, v);
            }
            __syncthreads();
#pragma unroll 8
            for (int kk = 0; kk < 32; kk++) {
                ulonglong2 xa = *(const ulonglong2*)&Ps[(sub*32+kk)*132 + txc*8];
                ulonglong2 xb = *(const ulonglong2*)&Ps[(sub*32+kk)*132 + txc*8 + 4];
#pragma unroll
                for (int i = 0; i < 4; i++) {
                    u64 w = Vd[(tyc*4+i)*33 + kk];
                    oacc[i][0] = ffma2(w, xa.x, oacc[i][0]);
                    oacc[i][1] = ffma2(w, xa.y, oacc[i][1]);
                    oacc[i][2] = ffma2(w, xb.x, oacc[i][2]);
                    oacc[i][3] = ffma2(w, xb.y, oacc[i][3]);
                }
            }
        }
    }
    __syncthreads();
#pragma unroll
    for (int jp = 0; jp < 4; jp++) {
        int tp = txc*4 + jp;
        float inve = 1.f / ssum[2*tp];
        float invo = 1.f / ssum[2*tp + 1];
        float vals[4][2];
#pragma unroll
        for (int i = 0; i < 4; i++) {
            int d = tyc*4 + i;
            float be = 0.f, bo = 0.f;
#pragma unroll
            for (int dt = 0; dt < 9; dt++) {
                float rv = rvs[dt*68 + d];
                be += bacc[(2*tp)*10 + dt]   * rv;
                bo += bacc[(2*tp+1)*10 + dt] * rv;
            }
            float2 f = funpack2(oacc[i][jp]);
            vals[i][0] = (f.x + be)*inve;
            vals[i][1] = (f.y + bo)*invo;
        }
#pragma unroll
        for (int pp = 0; pp < 2; pp++) {
            int P = tyc*2 + pp;
            size_t pbase = ((size_t)(b*8 + h)*32 + P)*516 + t0 + 2*tp + 1;
            u32 h0, l0, h1, l1;
            split2(vals[2*pp][0], vals[2*pp+1][0], h0, l0);
            split2(vals[2*pp][1], vals[2*pp+1][1], h1, l1);
            PanHi[pbase]     = h0; PanLo[pbase]     = l0;
            PanHi[pbase + 1] = h1; PanLo[pbase + 1] = l1;
        }
    }
}

// ---------------- channel LayerNorm + packed panel output ----------------------
__global__ void k_ln(float* __restrict__ hbuf, const float* __restrict__ yv,
                     const float* __restrict__ g, const float* __restrict__ bb,
                     u32* __restrict__ PanHi, u32* __restrict__ PanLo,
                     int maskOut) {
    int tx = threadIdx.x, ty = threadIdx.y;
    int t = blockIdx.x*16 + tx, b = blockIdx.y;
    float s = 0.f, s2 = 0.f;
    for (int p = ty; p < 256; p += 16) {
        size_t idx = ((size_t)b*C + 2*p)*T + t;
        float v0 = hbuf[idx] + yv[idx];
        float v1 = hbuf[idx + T] + yv[idx + T];
        s += v0 + v1; s2 += v0*v0 + v1*v1;
    }
    __shared__ float rs[16][17], rs2[16][17];
    rs[ty][tx] = s; rs2[ty][tx] = s2;
    __syncthreads();
    if (ty == 0) {
        for (int j = 1; j < 16; j++) { s += rs[j][tx]; s2 += rs2[j][tx]; }
        float m = s / C;
        float var = s2 / C - m*m;
        rs[0][tx] = m;
        rs2[0][tx] = rsqrtf(var + 1e-5f);
    }
    __syncthreads();
    float m = rs[0][tx], r = rs2[0][tx];
    float mk = g_mask[b*T + t];
    float fm = maskOut ? mk : 1.f;
    for (int p = ty; p < 256; p += 16) {
        size_t idx = ((size_t)b*C + 2*p)*T + t;
        float v0 = hbuf[idx] + yv[idx];
        float v1 = hbuf[idx + T] + yv[idx + T];
        v0 = (v0 - m)*r*g[2*p]   + bb[2*p];
        v1 = (v1 - m)*r*g[2*p+1] + bb[2*p+1];
        hbuf[idx]     = v0 * fm;
        hbuf[idx + T] = v1 * fm;
        u32 hv, lv; split2(v0*mk, v1*mk, hv, lv);
        size_t pb = ((size_t)(b*8 + (p >> 5))*32 + (p & 31))*516 + t + 1;
        PanHi[pb] = hv; PanLo[pb] = lv;
    }
}

// ---------------- launch -------------------------------------------------------
extern "C" void kernel_launch(void* const* d_in, const int* in_sizes, int n_in,
                              void* d_out, int out_size) {
    const int*   x    = (const int*)d_in[0];
    const int*   xlen = (const int*)d_in[1];
    const float* emb  = (const float*)d_in[2];
    const float* Wq = (const float*)d_in[3],  *bq = (const float*)d_in[4];
    const float* Wk = (const float*)d_in[5],  *bk = (const float*)d_in[6];
    const float* Wv = (const float*)d_in[7],  *bv = (const float*)d_in[8];
    const float* Wo = (const float*)d_in[9],  *bo = (const float*)d_in[10];
    const float* rel_k = (const float*)d_in[11], *rel_v = (const float*)d_in[12];
    const float* ln1g = (const float*)d_in[13], *ln1b = (const float*)d_in[14];
    const float* ln2g = (const float*)d_in[15], *ln2b = (const float*)d_in[16];
    const float* w1 = (const float*)d_in[17], *b1 = (const float*)d_in[18];
    const float* w2 = (const float*)d_in[19], *b2 = (const float*)d_in[20];
    const float* pw = (const float*)d_in[21], *pbv = (const float*)d_in[22];
    float* out = (float*)d_out;
    size_t SZ = (size_t)B*C*T;

    float *ph,*pqkv,*py,*pb3;
    u32 *x5h,*x5l,*x2h,*x2l,*wqh,*wql,*woh,*wol,*w1h,*w1l,*w2h,*w2l,*pjh,*pjl;
    cudaGetSymbolAddress((void**)&ph,   g_h);
    cudaGetSymbolAddress((void**)&pqkv, g_qkv);
    cudaGetSymbolAddress((void**)&py,   g_y);
    cudaGetSymbolAddress((void**)&pb3,  g_b3);
    cudaGetSymbolAddress((void**)&x5h,  g_px512_hi);
    cudaGetSymbolAddress((void**)&x5l,  g_px512_lo);
    cudaGetSymbolAddress((void**)&x2h,  g_px2048_hi);
    cudaGetSymbolAddress((void**)&x2l,  g_px2048_lo);
    cudaGetSymbolAddress((void**)&wqh,  g_wqkv_hi);
    cudaGetSymbolAddress((void**)&wql,  g_wqkv_lo);
    cudaGetSymbolAddress((void**)&woh,  g_wo_hi);
    cudaGetSymbolAddress((void**)&wol,  g_wo_lo);
    cudaGetSymbolAddress((void**)&w1h,  g_w1_hi);
    cudaGetSymbolAddress((void**)&w1l,  g_w1_lo);
    cudaGetSymbolAddress((void**)&w2h,  g_w2_hi);
    cudaGetSymbolAddress((void**)&w2l,  g_w2_lo);
    cudaGetSymbolAddress((void**)&pjh,  g_pj_hi);
    cudaGetSymbolAddress((void**)&pjl,  g_pj_lo);

    const int SMB = 64*136*4*4;
    static int attr_set = 0;
    static cudaStream_t s2;
    static cudaEvent_t evFork, evPack;
    if (!attr_set) {
        cudaFuncSetAttribute((void*)k_mma_f<1,128,0>, cudaFuncAttributeMaxDynamicSharedMemorySize, SMB);
        cudaFuncSetAttribute((void*)k_mma_f<3,128,0>, cudaFuncAttributeMaxDynamicSharedMemorySize, SMB);
        cudaFuncSetAttribute((void*)k_mma_f<3,128,1>, cudaFuncAttributeMaxDynamicSharedMemorySize, SMB);
        cudaFuncSetAttribute((void*)k_flash, cudaFuncAttributeMaxDynamicSharedMemorySize, FSM_TOTAL);
        cudaStreamCreateWithFlags(&s2, cudaStreamNonBlocking);
        cudaEventCreateWithFlags(&evFork, cudaEventDisableTiming);
        cudaEventCreateWithFlags(&evPack, cudaEventDisableTiming);
        attr_set = 1;
    }

    dim3 tb(32,8);
    k_zpad<<<40, 256>>>();
    k_embed<<<dim3(T/32, B), tb>>>(x, xlen, emb, out, out + 4*SZ);
    k_packwf<<<dim3(8, 32, 1), 256>>>(pw, 1.f, pjh, pjl, C, 1, 32, 8, 0);
    k_bias3<<<dim3(6, LYR), 256>>>(bq, bk, bv, pb3);
    // pack layer 0 weights on default stream
    k_packall<<<3584, 256>>>(Wq, Wk, Wv, Wo, w1, w2,
                             wqh, wql, woh, wol, w1h, w1l, w2h, w2l);

    for (int i = 0; i < LYR; i++) {
        int par = i & 1, nxt = par ^ 1;
        u32 *cqh = wqh + par*QS2,  *cql = wql + par*QS2;
        u32 *coh = woh + par*OS2,  *col = wol + par*OS2;
        u32 *c1h = w1h + par*W1S2, *c1l = w1l + par*W1S2;
        u32 *c2h = w2h + par*W2S2, *c2l = w2l + par*W2S2;

        // overlap: pack layer i+1 weights on side stream
        if (i + 1 < LYR) {
            cudaEventRecord(evFork, 0);
            cudaStreamWaitEvent(s2, evFork, 0);
            size_t j = (size_t)(i + 1);
            k_packall<<<3584, 256, 0, s2>>>(Wq + j*C*C, Wk + j*C*C, Wv + j*C*C, Wo + j*C*C,
                                            w1 + j*DFF*C*3, w2 + j*C*DFF*3,
                                            wqh + nxt*QS2, wql + nxt*QS2,
                                            woh + nxt*OS2, wol + nxt*OS2,
                                            w1h + nxt*W1S2, w1l + nxt*W1S2,
                                            w2h + nxt*W2S2, w2l + nxt*W2S2);
            cudaEventRecord(evPack, s2);
        }

        k_mma_f<1,128,0><<<dim3(4, 12, B), 256, SMB>>>(cqh, cql, x5h, x5l,
            pb3 + i*1536, pqkv, pqkv, 1536, 0, 0, 0, C, 0, 0);
        k_flash<<<dim3(T/128, B*H), 256, FSM_TOTAL>>>(pqkv, x5h, x5l,
            rel_k + (size_t)i*NREL*DK, rel_v + (size_t)i*NREL*DK);
        k_mma_f<1,128,0><<<dim3(4, 4, B), 256, SMB>>>(coh, col, x5h, x5l,
            bo + i*C, py, py, C, 0, 0, 0, C, 0, 0);
        k_ln<<<dim3(T/16, B), dim3(16,16)>>>(ph, py, ln1g + i*C, ln1b + i*C, x5h, x5l, 0);

        k_mma_f<3,128,1><<<dim3(4, 16, B), 256, SMB>>>(c1h, c1l, x5h, x5l,
            b1 + i*DFF, 0, 0, 0, x2h, x2l, 32, C, 1, 0);
        k_mma_f<3,128,0><<<dim3(4, 4, B), 256, SMB>>>(c2h, c2l, x2h, x2l,
            b2 + i*C, py, py, C, 0, 0, 0, DFF, 0, 1);
        k_ln<<<dim3(T/16, B), dim3(16,16)>>>(ph, py, ln2g + i*C, ln2b + i*C, x5h, x5l, 1);

        if (i + 1 < LYR) cudaStreamWaitEvent(0, evPack, 0);
    }

    k_copy4<<<(B*C*T)/1024, 256>>>((const float4*)ph, (float4*)(out + SZ));
    k_mma_f<1,128,0><<<dim3(4, 8, B), 256, SMB>>>(pjh, pjl, x5h, x5l, pbv,
        out + 2*SZ, out + 3*SZ, 512, 0, 0, 0, C, 0, 1);
}